// round 4
// baseline (speedup 1.0000x reference)
#include <cuda_runtime.h>
#include <math.h>

// ---------------- problem constants ----------------
#define BATCH   4
#define SEQ     2048
#define DMODEL  1024
#define NHEADS  16
#define DK      64                 // DMODEL / NHEADS
#define MROWS   (BATCH * SEQ)      // 8192
#define QKVCOLS (3 * DMODEL)       // 3072

// ---------------- scratch (device globals: allocation-guard safe) ----------------
__device__ float g_qkv[(size_t)MROWS * QKVCOLS];   // 96 MB: [8192, 3072] row-major
__device__ float g_attn[(size_t)MROWS * DMODEL];   // 32 MB: [8192, 1024] row-major

// =================================================================
// SGEMM: C[M,N] = A[M,K] @ B[K,N], all row-major, fp32.
// BM=BN=128, BK=8, 256 threads, 8x8 microtile per thread.
// Requires M%128==0, N%128==0, K%8==0 (true for all our shapes).
// =================================================================
__global__ __launch_bounds__(256, 2)
void sgemm128(const float* __restrict__ A, const float* __restrict__ B,
              float* __restrict__ C, int M, int N, int K)
{
    __shared__ float As[8][132];   // transposed A tile, padded
    __shared__ float Bs[8][132];   // B tile, padded (132*4B keeps 16B alignment)

    const int tid       = threadIdx.x;
    const int block_row = blockIdx.y * 128;
    const int block_col = blockIdx.x * 128;

    // A tile loads: 128x8 floats = 256 float4, one per thread
    const int aRow = tid >> 1;            // 0..127
    const int aCol = (tid & 1) * 4;       // 0 or 4
    // B tile loads: 8x128 floats = 256 float4, one per thread
    const int bRow = tid >> 5;            // 0..7
    const int bCol = (tid & 31) * 4;      // 0..124

    const float* Aptr = A + (size_t)(block_row + aRow) * K + aCol;
    const float* Bptr = B + (size_t)bRow * N + block_col + bCol;

    const int tRow = (tid >> 4) * 8;      // 0..120
    const int tCol = (tid & 15) * 8;      // 0..120

    float acc[8][8];
    #pragma unroll
    for (int i = 0; i < 8; i++)
        #pragma unroll
        for (int j = 0; j < 8; j++) acc[i][j] = 0.0f;

    for (int k0 = 0; k0 < K; k0 += 8) {
        float4 a = *(const float4*)Aptr;
        float4 b = *(const float4*)Bptr;
        As[aCol + 0][aRow] = a.x;
        As[aCol + 1][aRow] = a.y;
        As[aCol + 2][aRow] = a.z;
        As[aCol + 3][aRow] = a.w;
        *(float4*)&Bs[bRow][bCol] = b;
        __syncthreads();

        #pragma unroll
        for (int k = 0; k < 8; k++) {
            float ra[8], rb[8];
            #pragma unroll
            for (int i = 0; i < 8; i++) ra[i] = As[k][tRow + i];
            #pragma unroll
            for (int j = 0; j < 8; j++) rb[j] = Bs[k][tCol + j];
            #pragma unroll
            for (int i = 0; i < 8; i++)
                #pragma unroll
                for (int j = 0; j < 8; j++)
                    acc[i][j] += ra[i] * rb[j];
        }
        __syncthreads();
        Aptr += 8;
        Bptr += (size_t)8 * N;
    }

    #pragma unroll
    for (int i = 0; i < 8; i++) {
        float* c = C + (size_t)(block_row + tRow + i) * N + block_col + tCol;
        *(float4*)(c)     = make_float4(acc[i][0], acc[i][1], acc[i][2], acc[i][3]);
        *(float4*)(c + 4) = make_float4(acc[i][4], acc[i][5], acc[i][6], acc[i][7]);
    }
}

// =================================================================
// Flash attention (fp32, causal). One block per (q-tile, batch*head).
// BR=64 query rows, BC=32 key rows per inner tile, 256 threads (16x16).
// Each thread: 4 rows; S microtile 4x2; O microtile 4x4.
// =================================================================
#define BR 64
#define BC 32

__global__ __launch_bounds__(256)
void flash_attn_kernel(const float* __restrict__ qkv, float* __restrict__ attn_out)
{
    __shared__ float Qs[BR][DK + 4];   // 17408 B
    __shared__ float Ks[BC][DK + 4];   //  8704 B
    __shared__ float Vs[BC][DK + 4];   //  8704 B
    __shared__ float Ps[BR][BC + 4];   //  9216 B   total 44032 B < 48KB

    const int bh = blockIdx.y;
    const int b  = bh >> 4;
    const int h  = bh & 15;
    const int qt = blockIdx.x;
    const int q0 = qt * BR;
    const int tid = threadIdx.x;

    const float* Qbase = qkv + (size_t)b * SEQ * QKVCOLS + h * DK;
    const float* Kbase = Qbase + DMODEL;
    const float* Vbase = Qbase + 2 * DMODEL;

    // load Q tile: 64 x 64 floats = 1024 float4
    for (int i = tid; i < BR * (DK / 4); i += 256) {
        int r = i >> 4;             // 16 float4 per row
        int c = (i & 15) << 2;
        *(float4*)&Qs[r][c] = *(const float4*)(Qbase + (size_t)(q0 + r) * QKVCOLS + c);
    }

    const int tx = tid & 15;
    const int ty = tid >> 4;
    const int r0 = ty * 4;

    float m_i[4], l_i[4], O_acc[4][4];
    #pragma unroll
    for (int i = 0; i < 4; i++) {
        m_i[i] = -INFINITY;
        l_i[i] = 0.0f;
        #pragma unroll
        for (int j = 0; j < 4; j++) O_acc[i][j] = 0.0f;
    }

    const int kt_max = 2 * qt + 1;     // causal: only tiles with k0 <= q0+BR-1
    for (int kt = 0; kt <= kt_max; kt++) {
        const int k0 = kt * BC;

        __syncthreads();   // previous iter done with Ks/Vs/Ps (also covers Q load on iter 0)
        for (int i = tid; i < BC * (DK / 4); i += 256) {
            int r = i >> 4;
            int c = (i & 15) << 2;
            *(float4*)&Ks[r][c] = *(const float4*)(Kbase + (size_t)(k0 + r) * QKVCOLS + c);
            *(float4*)&Vs[r][c] = *(const float4*)(Vbase + (size_t)(k0 + r) * QKVCOLS + c);
        }
        __syncthreads();

        // S = Q K^T : 4x2 per thread
        float s[4][2];
        #pragma unroll
        for (int i = 0; i < 4; i++) { s[i][0] = 0.0f; s[i][1] = 0.0f; }
        #pragma unroll 8
        for (int k = 0; k < DK; k++) {
            float qr[4], kc0, kc1;
            #pragma unroll
            for (int i = 0; i < 4; i++) qr[i] = Qs[r0 + i][k];
            kc0 = Ks[tx * 2 + 0][k];
            kc1 = Ks[tx * 2 + 1][k];
            #pragma unroll
            for (int i = 0; i < 4; i++) {
                s[i][0] += qr[i] * kc0;
                s[i][1] += qr[i] * kc1;
            }
        }

        // scale + causal mask
        #pragma unroll
        for (int i = 0; i < 4; i++) {
            int qi = q0 + r0 + i;
            #pragma unroll
            for (int j = 0; j < 2; j++) {
                int ki = k0 + tx * 2 + j;
                s[i][j] = (ki <= qi) ? s[i][j] * 0.125f : -INFINITY;
            }
        }

        // row max across 16 tx lanes
        float mt[4];
        #pragma unroll
        for (int i = 0; i < 4; i++) mt[i] = fmaxf(s[i][0], s[i][1]);
        #pragma unroll
        for (int off = 8; off >= 1; off >>= 1)
            #pragma unroll
            for (int i = 0; i < 4; i++)
                mt[i] = fmaxf(mt[i], __shfl_xor_sync(0xffffffffu, mt[i], off));

        float mnew[4], alpha[4];
        #pragma unroll
        for (int i = 0; i < 4; i++) {
            mnew[i]  = fmaxf(m_i[i], mt[i]);          // finite: col 0 always valid
            alpha[i] = __expf(m_i[i] - mnew[i]);      // exp(-inf)=0 on first tile
        }

        float p[4][2], rowsum[4];
        #pragma unroll
        for (int i = 0; i < 4; i++) {
            p[i][0] = __expf(s[i][0] - mnew[i]);
            p[i][1] = __expf(s[i][1] - mnew[i]);
            rowsum[i] = p[i][0] + p[i][1];
        }
        #pragma unroll
        for (int off = 8; off >= 1; off >>= 1)
            #pragma unroll
            for (int i = 0; i < 4; i++)
                rowsum[i] += __shfl_xor_sync(0xffffffffu, rowsum[i], off);

        #pragma unroll
        for (int i = 0; i < 4; i++) {
            l_i[i] = l_i[i] * alpha[i] + rowsum[i];
            m_i[i] = mnew[i];
            #pragma unroll
            for (int j = 0; j < 4; j++) O_acc[i][j] *= alpha[i];
            Ps[r0 + i][tx * 2 + 0] = p[i][0];
            Ps[r0 + i][tx * 2 + 1] = p[i][1];
        }
        __syncthreads();

        // O += P @ V : 4x4 per thread
        #pragma unroll 8
        for (int j = 0; j < BC; j++) {
            float pv[4], vv[4];
            #pragma unroll
            for (int i = 0; i < 4; i++) pv[i] = Ps[r0 + i][j];
            #pragma unroll
            for (int c = 0; c < 4; c++) vv[c] = Vs[j][tx * 4 + c];
            #pragma unroll
            for (int i = 0; i < 4; i++)
                #pragma unroll
                for (int c = 0; c < 4; c++)
                    O_acc[i][c] += pv[i] * vv[c];
        }
    }

    // normalize + write: attn_out[(b*SEQ+row), h*64 + tx*4 .. +3]
    #pragma unroll
    for (int i = 0; i < 4; i++) {
        float inv = 1.0f / l_i[i];
        int row = q0 + r0 + i;
        float* dst = attn_out + (size_t)(b * SEQ + row) * DMODEL + h * DK + tx * 4;
        *(float4*)dst = make_float4(O_acc[i][0] * inv, O_acc[i][1] * inv,
                                    O_acc[i][2] * inv, O_acc[i][3] * inv);
    }
}

// =================================================================
// kernel_launch: qkv GEMM -> flash attention -> out GEMM
// =================================================================
extern "C" void kernel_launch(void* const* d_in, const int* in_sizes, int n_in,
                              void* d_out, int out_size)
{
    const float* x     = (const float*)d_in[0];   // (4,2048,1024) fp32
    const float* w_qkv = (const float*)d_in[1];   // (1024,3072)   fp32
    const float* w_out = (const float*)d_in[2];   // (1024,1024)   fp32
    float*       out   = (float*)d_out;           // (4,2048,1024) fp32

    float *qkv_buf, *attn_buf;
    cudaGetSymbolAddress((void**)&qkv_buf,  g_qkv);
    cudaGetSymbolAddress((void**)&attn_buf, g_attn);

    // 1) QKV projection: [8192,1024] @ [1024,3072] -> [8192,3072]
    {
        dim3 grid(QKVCOLS / 128, MROWS / 128);   // (24, 64)
        sgemm128<<<grid, 256>>>(x, w_qkv, qkv_buf, MROWS, QKVCOLS, DMODEL);
    }

    // 2) causal flash attention per (q-tile, batch*head) -> [8192,1024]
    {
        dim3 grid(SEQ / BR, BATCH * NHEADS);     // (32, 64)
        flash_attn_kernel<<<grid, 256>>>(qkv_buf, attn_buf);
    }

    // 3) output projection: [8192,1024] @ [1024,1024] -> [8192,1024]
    {
        dim3 grid(DMODEL / 128, MROWS / 128);    // (8, 64)
        sgemm128<<<grid, 256>>>(attn_buf, w_out, out, MROWS, DMODEL, DMODEL);
    }
}

// round 5
// speedup vs baseline: 3.5421x; 3.5421x over previous
#include <cuda_runtime.h>
#include <math.h>
#include <stdint.h>

// ---------------- problem constants ----------------
#define BATCH   4
#define SEQ     2048
#define DMODEL  1024
#define NHEADS  16
#define DK      64
#define MROWS   (BATCH * SEQ)      // 8192
#define QKVCOLS (3 * DMODEL)       // 3072

// ---------------- scratch ----------------
__device__ float g_qkv[(size_t)MROWS * QKVCOLS];   // 96 MB
__device__ float g_attn[(size_t)MROWS * DMODEL];   // 32 MB

// ---------------- tf32 helpers ----------------
__device__ __forceinline__ uint32_t f2tf(float x) {
    uint32_t r;
    asm("cvt.rna.tf32.f32 %0, %1;" : "=r"(r) : "f"(x));
    return r;
}

// D = A(16x8, row) * B(8x8, col) + D, tf32 in, fp32 accum
__device__ __forceinline__ void mma8(float* c, const uint32_t* a, const uint32_t* b) {
    asm volatile(
        "mma.sync.aligned.m16n8k8.row.col.f32.tf32.tf32.f32 "
        "{%0,%1,%2,%3}, {%4,%5,%6,%7}, {%8,%9}, {%0,%1,%2,%3};"
        : "+f"(c[0]), "+f"(c[1]), "+f"(c[2]), "+f"(c[3])
        : "r"(a[0]), "r"(a[1]), "r"(a[2]), "r"(a[3]), "r"(b[0]), "r"(b[1]));
}

// =================================================================
// TF32 GEMM: C[M,N] = A[M,K] @ B[K,N], row-major fp32 in/out.
// BM=BN=128, BK=32, 256 threads = 8 warps (2x4), warp tile 64x32.
// =================================================================
#define AST 36     // A smem row stride (== 4 mod 32: conflict-free frag loads)
#define BST 136    // B smem row stride (== 8 mod 32)

__global__ __launch_bounds__(256, 2)
void gemm_tf32(const float* __restrict__ A, const float* __restrict__ B,
               float* __restrict__ C, int M, int N, int K)
{
    __shared__ uint32_t As[128 * AST];   // 18.4 KB
    __shared__ uint32_t Bs[32 * BST];    // 17.4 KB

    const int tid  = threadIdx.x;
    const int lane = tid & 31, warp = tid >> 5;
    const int g    = lane >> 2, tig = lane & 3;
    const int wr   = warp >> 2, wc  = warp & 3;     // 2 x 4 warp grid
    const int br   = blockIdx.y * 128, bc = blockIdx.x * 128;

    float acc[4][4][4];
    #pragma unroll
    for (int mt = 0; mt < 4; mt++)
        #pragma unroll
        for (int nt = 0; nt < 4; nt++)
            #pragma unroll
            for (int j = 0; j < 4; j++) acc[mt][nt][j] = 0.0f;

    for (int k0 = 0; k0 < K; k0 += 32) {
        __syncthreads();
        // A tile 128x32 -> tf32 smem (STS.128, conflict-free)
        #pragma unroll
        for (int i = tid; i < 1024; i += 256) {
            int row = i >> 3, c4 = (i & 7) * 4;
            float4 v = *(const float4*)(A + (size_t)(br + row) * K + k0 + c4);
            uint4 t = make_uint4(f2tf(v.x), f2tf(v.y), f2tf(v.z), f2tf(v.w));
            *(uint4*)(As + row * AST + c4) = t;
        }
        // B tile 32x128
        #pragma unroll
        for (int i = tid; i < 1024; i += 256) {
            int row = i >> 5, c4 = (i & 31) * 4;
            float4 v = *(const float4*)(B + (size_t)(k0 + row) * N + bc + c4);
            uint4 t = make_uint4(f2tf(v.x), f2tf(v.y), f2tf(v.z), f2tf(v.w));
            *(uint4*)(Bs + row * BST + c4) = t;
        }
        __syncthreads();

        #pragma unroll
        for (int kc = 0; kc < 4; kc++) {
            uint32_t a[4][4], b[4][2];
            #pragma unroll
            for (int mt = 0; mt < 4; mt++) {
                const uint32_t* p = As + (wr * 64 + mt * 16 + g) * AST + kc * 8 + tig;
                a[mt][0] = p[0];
                a[mt][1] = p[8 * AST];
                a[mt][2] = p[4];
                a[mt][3] = p[8 * AST + 4];
            }
            #pragma unroll
            for (int nt = 0; nt < 4; nt++) {
                const uint32_t* p = Bs + (kc * 8 + tig) * BST + wc * 32 + nt * 8 + g;
                b[nt][0] = p[0];
                b[nt][1] = p[4 * BST];
            }
            #pragma unroll
            for (int mt = 0; mt < 4; mt++)
                #pragma unroll
                for (int nt = 0; nt < 4; nt++)
                    mma8(acc[mt][nt], a[mt], b[nt]);
        }
    }

    // epilogue: C layout rows (g, g+8), cols (2tig, 2tig+1)
    #pragma unroll
    for (int mt = 0; mt < 4; mt++) {
        int row = br + wr * 64 + mt * 16 + g;
        #pragma unroll
        for (int nt = 0; nt < 4; nt++) {
            int col = bc + wc * 32 + nt * 8 + 2 * tig;
            *(float2*)(C + (size_t)row * N + col)       = make_float2(acc[mt][nt][0], acc[mt][nt][1]);
            *(float2*)(C + (size_t)(row + 8) * N + col) = make_float2(acc[mt][nt][2], acc[mt][nt][3]);
        }
    }
}

// =================================================================
// TF32 flash attention, causal. BR=BC=64, 128 threads (4 warps).
// Warp w owns q rows [16w, 16w+16). Q frags register-resident.
// smem (dynamic, 53248 B): Ps[64x68] (Q staging, then P), Ks[64x68], Vs[64x72]
// =================================================================
#define PST 68
#define KST 68
#define VST 72

__global__ __launch_bounds__(128)
void flash_tf32(const float* __restrict__ qkv, float* __restrict__ outp)
{
    extern __shared__ uint32_t sm[];
    uint32_t* Ps = sm;                       // 64*68
    uint32_t* Ks = sm + 64 * PST;            // 64*68
    uint32_t* Vs = Ks + 64 * KST;            // 64*72

    const int tid  = threadIdx.x;
    const int lane = tid & 31, warp = tid >> 5;
    const int g    = lane >> 2, tig = lane & 3;
    const int bh   = blockIdx.y, b = bh >> 4, h = bh & 15;
    const int qt   = gridDim.x - 1 - blockIdx.x;   // heavy tiles first
    const int q0   = qt * 64;

    const float* Qb = qkv + (size_t)b * SEQ * QKVCOLS + h * DK;
    const float* Kb = Qb + DMODEL;
    const float* Vb = Qb + 2 * DMODEL;

    // stage Q (scaled by 1/sqrt(dk)=0.125) into Ps, tf32
    for (int i = tid; i < 64 * 16; i += 128) {
        int row = i >> 4, c4 = (i & 15) * 4;
        float4 v = *(const float4*)(Qb + (size_t)(q0 + row) * QKVCOLS + c4);
        uint4 t = make_uint4(f2tf(v.x * 0.125f), f2tf(v.y * 0.125f),
                             f2tf(v.z * 0.125f), f2tf(v.w * 0.125f));
        *(uint4*)(Ps + row * PST + c4) = t;
    }
    __syncthreads();

    // extract Q fragments (this warp's 16 rows) into registers
    uint32_t aq[8][4];
    #pragma unroll
    for (int kc = 0; kc < 8; kc++) {
        const uint32_t* p = Ps + (warp * 16 + g) * PST + kc * 8 + tig;
        aq[kc][0] = p[0];
        aq[kc][1] = p[8 * PST];
        aq[kc][2] = p[4];
        aq[kc][3] = p[8 * PST + 4];
    }

    float m0 = -INFINITY, m1 = -INFINITY, l0 = 0.0f, l1 = 0.0f;
    float o[8][4];
    #pragma unroll
    for (int nt = 0; nt < 8; nt++)
        #pragma unroll
        for (int j = 0; j < 4; j++) o[nt][j] = 0.0f;

    for (int kt = 0; kt <= qt; kt++) {
        const int k0 = kt * 64;

        __syncthreads();   // everyone done with prev Ks/Vs
        for (int i = tid; i < 64 * 16; i += 128) {
            int row = i >> 4, c4 = (i & 15) * 4;
            float4 kv = *(const float4*)(Kb + (size_t)(k0 + row) * QKVCOLS + c4);
            *(uint4*)(Ks + row * KST + c4) =
                make_uint4(f2tf(kv.x), f2tf(kv.y), f2tf(kv.z), f2tf(kv.w));
            float4 vv = *(const float4*)(Vb + (size_t)(k0 + row) * QKVCOLS + c4);
            *(uint4*)(Vs + row * VST + c4) =
                make_uint4(f2tf(vv.x), f2tf(vv.y), f2tf(vv.z), f2tf(vv.w));
        }
        __syncthreads();

        // S = Qs @ K^T : 8 n-tiles of 8 keys
        float s[8][4];
        #pragma unroll
        for (int nt = 0; nt < 8; nt++) {
            s[nt][0] = s[nt][1] = s[nt][2] = s[nt][3] = 0.0f;
            #pragma unroll
            for (int kc = 0; kc < 8; kc++) {
                uint32_t bk[2];
                const uint32_t* p = Ks + (nt * 8 + g) * KST + kc * 8 + tig;
                bk[0] = p[0];
                bk[1] = p[4];
                mma8(s[nt], aq[kc], bk);
            }
        }

        // causal mask: only diagonal tile needs it
        if (kt == qt) {
            int r0 = warp * 16 + g;   // local q row
            #pragma unroll
            for (int nt = 0; nt < 8; nt++) {
                int c = nt * 8 + 2 * tig;
                if (c     > r0)     s[nt][0] = -INFINITY;
                if (c + 1 > r0)     s[nt][1] = -INFINITY;
                if (c     > r0 + 8) s[nt][2] = -INFINITY;
                if (c + 1 > r0 + 8) s[nt][3] = -INFINITY;
            }
        }

        // row maxima (rows g and g+8), reduce across the 4 lanes of the quad
        float mt0 = -INFINITY, mt1 = -INFINITY;
        #pragma unroll
        for (int nt = 0; nt < 8; nt++) {
            mt0 = fmaxf(mt0, fmaxf(s[nt][0], s[nt][1]));
            mt1 = fmaxf(mt1, fmaxf(s[nt][2], s[nt][3]));
        }
        mt0 = fmaxf(mt0, __shfl_xor_sync(0xffffffffu, mt0, 1));
        mt0 = fmaxf(mt0, __shfl_xor_sync(0xffffffffu, mt0, 2));
        mt1 = fmaxf(mt1, __shfl_xor_sync(0xffffffffu, mt1, 1));
        mt1 = fmaxf(mt1, __shfl_xor_sync(0xffffffffu, mt1, 2));

        float mn0 = fmaxf(m0, mt0), mn1 = fmaxf(m1, mt1);
        float al0 = __expf(m0 - mn0), al1 = __expf(m1 - mn1);

        float rs0 = 0.0f, rs1 = 0.0f;
        #pragma unroll
        for (int nt = 0; nt < 8; nt++) {
            s[nt][0] = __expf(s[nt][0] - mn0);
            s[nt][1] = __expf(s[nt][1] - mn0);
            s[nt][2] = __expf(s[nt][2] - mn1);
            s[nt][3] = __expf(s[nt][3] - mn1);
            rs0 += s[nt][0] + s[nt][1];
            rs1 += s[nt][2] + s[nt][3];
        }
        rs0 += __shfl_xor_sync(0xffffffffu, rs0, 1);
        rs0 += __shfl_xor_sync(0xffffffffu, rs0, 2);
        rs1 += __shfl_xor_sync(0xffffffffu, rs1, 1);
        rs1 += __shfl_xor_sync(0xffffffffu, rs1, 2);

        l0 = l0 * al0 + rs0;
        l1 = l1 * al1 + rs1;
        m0 = mn0;
        m1 = mn1;
        #pragma unroll
        for (int nt = 0; nt < 8; nt++) {
            o[nt][0] *= al0; o[nt][1] *= al0;
            o[nt][2] *= al1; o[nt][3] *= al1;
        }

        // write P (tf32) to this warp's private rows of Ps, then PV
        __syncwarp();
        {
            uint32_t* pr0 = Ps + (warp * 16 + g) * PST;
            uint32_t* pr1 = pr0 + 8 * PST;
            #pragma unroll
            for (int nt = 0; nt < 8; nt++) {
                int c = nt * 8 + 2 * tig;
                pr0[c]     = f2tf(s[nt][0]);
                pr0[c + 1] = f2tf(s[nt][1]);
                pr1[c]     = f2tf(s[nt][2]);
                pr1[c + 1] = f2tf(s[nt][3]);
            }
        }
        __syncwarp();

        // O += P @ V
        #pragma unroll
        for (int kc = 0; kc < 8; kc++) {
            uint32_t ap[4];
            const uint32_t* pp = Ps + (warp * 16 + g) * PST + kc * 8 + tig;
            ap[0] = pp[0];
            ap[1] = pp[8 * PST];
            ap[2] = pp[4];
            ap[3] = pp[8 * PST + 4];
            #pragma unroll
            for (int nt = 0; nt < 8; nt++) {
                uint32_t bv[2];
                const uint32_t* pv = Vs + (kc * 8 + tig) * VST + nt * 8 + g;
                bv[0] = pv[0];
                bv[1] = pv[4 * VST];
                mma8(o[nt], ap, bv);
            }
        }
    }

    // normalize + write out
    float i0 = 1.0f / l0, i1 = 1.0f / l1;
    int r0 = q0 + warp * 16 + g;
    float* dst0 = outp + (size_t)(b * SEQ + r0) * DMODEL + h * DK;
    float* dst1 = dst0 + (size_t)8 * DMODEL;
    #pragma unroll
    for (int nt = 0; nt < 8; nt++) {
        int c = nt * 8 + 2 * tig;
        *(float2*)(dst0 + c) = make_float2(o[nt][0] * i0, o[nt][1] * i0);
        *(float2*)(dst1 + c) = make_float2(o[nt][2] * i1, o[nt][3] * i1);
    }
}

// =================================================================
// kernel_launch
// =================================================================
extern "C" void kernel_launch(void* const* d_in, const int* in_sizes, int n_in,
                              void* d_out, int out_size)
{
    const float* x     = (const float*)d_in[0];
    const float* w_qkv = (const float*)d_in[1];
    const float* w_out = (const float*)d_in[2];
    float*       out   = (float*)d_out;

    float *qkv_buf, *attn_buf;
    cudaGetSymbolAddress((void**)&qkv_buf,  g_qkv);
    cudaGetSymbolAddress((void**)&attn_buf, g_attn);

    const int flash_smem = (64 * PST + 64 * KST + 64 * VST) * 4;   // 53248 B
    cudaFuncSetAttribute(flash_tf32, cudaFuncAttributeMaxDynamicSharedMemorySize,
                         flash_smem);

    // 1) QKV projection: [8192,1024] @ [1024,3072]
    {
        dim3 grid(QKVCOLS / 128, MROWS / 128);   // (24, 64)
        gemm_tf32<<<grid, 256>>>(x, w_qkv, qkv_buf, MROWS, QKVCOLS, DMODEL);
    }

    // 2) causal flash attention
    {
        dim3 grid(SEQ / 64, BATCH * NHEADS);     // (32, 64)
        flash_tf32<<<grid, 128, flash_smem>>>(qkv_buf, attn_buf);
    }

    // 3) output projection: [8192,1024] @ [1024,1024]
    {
        dim3 grid(DMODEL / 128, MROWS / 128);    // (8, 64)
        gemm_tf32<<<grid, 256>>>(attn_buf, w_out, out, MROWS, DMODEL, DMODEL);
    }
}

// round 11
// speedup vs baseline: 3.7788x; 1.0668x over previous
#include <cuda_runtime.h>
#include <math.h>
#include <stdint.h>

// ---------------- problem constants ----------------
#define BATCH   4
#define SEQ     2048
#define DMODEL  1024
#define NHEADS  16
#define DK      64
#define MROWS   (BATCH * SEQ)      // 8192
#define QKVCOLS (3 * DMODEL)       // 3072

// ---------------- scratch ----------------
__device__ float g_qkv[(size_t)MROWS * QKVCOLS];    // 96 MB
__device__ float g_attn[(size_t)MROWS * DMODEL];    // 32 MB (tf32-rounded at write)
__device__ float g_xr[(size_t)MROWS * DMODEL];      // 32 MB (tf32-rounded x)
__device__ float g_wq[(size_t)DMODEL * QKVCOLS];    // 12 MB (rounded, [K][N])
__device__ float g_wo[(size_t)DMODEL * DMODEL];     //  4 MB (rounded, [K][N])

// ---------------- helpers ----------------
__device__ __forceinline__ uint32_t f2tf(float x) {
    uint32_t r;
    asm("cvt.rna.tf32.f32 %0, %1;" : "=r"(r) : "f"(x));
    return r;
}
__device__ __forceinline__ uint32_t smem_u32(const void* p) {
    uint32_t a;
    asm("{ .reg .u64 t; cvta.to.shared.u64 t, %1; cvt.u32.u64 %0, t; }" : "=r"(a) : "l"(p));
    return a;
}
__device__ __forceinline__ void cp16(uint32_t dst, const void* src) {
    asm volatile("cp.async.cg.shared.global [%0], [%1], 16;" :: "r"(dst), "l"(src));
}
__device__ __forceinline__ void cp_commit() { asm volatile("cp.async.commit_group;"); }
__device__ __forceinline__ void cp_wait1()  { asm volatile("cp.async.wait_group 1;"); }

// D(16x8) += A(16x8 row) * B(8x8 col), tf32 in, fp32 accum
__device__ __forceinline__ void mma8(float* c, const uint32_t* a, const uint32_t* b) {
    asm volatile(
        "mma.sync.aligned.m16n8k8.row.col.f32.tf32.tf32.f32 "
        "{%0,%1,%2,%3}, {%4,%5,%6,%7}, {%8,%9}, {%0,%1,%2,%3};"
        : "+f"(c[0]), "+f"(c[1]), "+f"(c[2]), "+f"(c[3])
        : "r"(a[0]), "r"(a[1]), "r"(a[2]), "r"(a[3]), "r"(b[0]), "r"(b[1]));
}

// =================================================================
// TF32 GEMM via mma.sync, cp.async 3-stage pipeline.
// C[M,N] = A[M,K] @ B[K,N], all row-major fp32 (pre-rounded to tf32).
// Block 128x256, 256 thr = 8 warps (2x4), warp tile 64x64, BK=32.
// Requires M%128==0, N%256==0, K%32==0.
// =================================================================
#define GST 3
#define ASTR 36                 // A smem row stride (== 4 mod 32)
#define BSTR 264                // B smem row stride (== 8 mod 32)
#define ASZ (128 * ASTR)        // 4608 u32 per stage
#define BSZ (32 * BSTR)         // 8448 u32 per stage
#define GSMEM ((GST * (ASZ + BSZ)) * 4)   // 156672 B

__global__ __launch_bounds__(256, 1)
void gemm_tf32_ca(const float* __restrict__ A, const float* __restrict__ B,
                  float* __restrict__ C, int N, int K)
{
    extern __shared__ uint32_t sm[];
    uint32_t* Asm = sm;                     // [GST][ASZ]
    uint32_t* Bsm = sm + GST * ASZ;         // [GST][BSZ]
    const uint32_t sA = smem_u32(Asm);
    const uint32_t sB = smem_u32(Bsm);

    const int tid  = threadIdx.x, lane = tid & 31, warp = tid >> 5;
    const int g    = lane >> 2, tig = lane & 3;
    const int wr   = warp >> 2, wc  = warp & 3;     // 2 x 4 warp grid
    const int bm   = blockIdx.y * 128, bn = blockIdx.x * 256;
    const int NK   = K / 32;

    // ---- async tile load: A 128x32, B 32x256 ----
    auto issue = [&](int s, int kt) {
        const float* Ag = A + (size_t)bm * K + kt * 32;
        const float* Bg = B + (size_t)(kt * 32) * N + bn;
        const uint32_t ao = sA + s * ASZ * 4;
        const uint32_t bo = sB + s * BSZ * 4;
        #pragma unroll
        for (int j = 0; j < 4; j++) {                 // A: 1024 x 16B chunks
            int idx = tid + j * 256;
            int row = idx >> 3, cc = (idx & 7) * 4;
            cp16(ao + (row * ASTR + cc) * 4, Ag + (size_t)row * K + cc);
        }
        #pragma unroll
        for (int j = 0; j < 8; j++) {                 // B: 2048 x 16B chunks
            int idx = tid + j * 256;
            int row = idx >> 6, cc = (idx & 63) * 4;
            cp16(bo + (row * BSTR + cc) * 4, Bg + (size_t)row * N + cc);
        }
        cp_commit();
    };

    float acc[4][8][4];
    #pragma unroll
    for (int mt = 0; mt < 4; mt++)
        #pragma unroll
        for (int nt = 0; nt < 8; nt++)
            #pragma unroll
            for (int j = 0; j < 4; j++) acc[mt][nt][j] = 0.0f;

    issue(0, 0);
    issue(1, 1);

    for (int kt = 0; kt < NK; kt++) {
        cp_wait1();            // tile kt resident (<=1 group pending: tile kt+1)
        __syncthreads();       // all threads see it; prev compute done
        if (kt + 2 < NK) issue((kt + 2) % GST, kt + 2);
        else             cp_commit();   // keep group accounting uniform

        const uint32_t* Ab = Asm + (kt % GST) * ASZ;
        const uint32_t* Bb = Bsm + (kt % GST) * BSZ;

        #pragma unroll
        for (int kc = 0; kc < 4; kc++) {
            uint32_t a[4][4], b[8][2];
            #pragma unroll
            for (int mt = 0; mt < 4; mt++) {
                const uint32_t* p = Ab + (wr * 64 + mt * 16 + g) * ASTR + kc * 8 + tig;
                a[mt][0] = p[0];
                a[mt][1] = p[8 * ASTR];
                a[mt][2] = p[4];
                a[mt][3] = p[8 * ASTR + 4];
            }
            #pragma unroll
            for (int nt = 0; nt < 8; nt++) {
                const uint32_t* p = Bb + (kc * 8 + tig) * BSTR + wc * 64 + nt * 8 + g;
                b[nt][0] = p[0];
                b[nt][1] = p[4 * BSTR];
            }
            #pragma unroll
            for (int mt = 0; mt < 4; mt++)
                #pragma unroll
                for (int nt = 0; nt < 8; nt++)
                    mma8(acc[mt][nt], a[mt], b[nt]);
        }
    }

    // epilogue: rows (g, g+8), cols (2tig, 2tig+1)
    #pragma unroll
    for (int mt = 0; mt < 4; mt++) {
        int row = bm + wr * 64 + mt * 16 + g;
        #pragma unroll
        for (int nt = 0; nt < 8; nt++) {
            int col = bn + wc * 64 + nt * 8 + 2 * tig;
            *(float2*)(C + (size_t)row * N + col)       = make_float2(acc[mt][nt][0], acc[mt][nt][1]);
            *(float2*)(C + (size_t)(row + 8) * N + col) = make_float2(acc[mt][nt][2], acc[mt][nt][3]);
        }
    }
}

// =================================================================
// prep: elementwise tf32 (RNA) rounding
// =================================================================
__global__ void round_tf32_kernel(const float4* __restrict__ in,
                                  float4* __restrict__ out, int n4)
{
    int i = blockIdx.x * blockDim.x + threadIdx.x;
    if (i < n4) {
        float4 v = in[i];
        out[i] = make_float4(__uint_as_float(f2tf(v.x)), __uint_as_float(f2tf(v.y)),
                             __uint_as_float(f2tf(v.z)), __uint_as_float(f2tf(v.w)));
    }
}

// =================================================================
// TF32 flash attention, causal (round-5 kernel; output tf32-rounded)
// BR=BC=64, 128 threads (4 warps), warp w owns q rows [16w,16w+16)
// =================================================================
#define PST 68
#define KST 68
#define VST 72

__global__ __launch_bounds__(128)
void flash_tf32(const float* __restrict__ qkv, float* __restrict__ outp)
{
    extern __shared__ uint32_t smf[];
    uint32_t* Ps = smf;
    uint32_t* Ks = smf + 64 * PST;
    uint32_t* Vs = Ks + 64 * KST;

    const int tid  = threadIdx.x;
    const int lane = tid & 31, warp = tid >> 5;
    const int g    = lane >> 2, tig = lane & 3;
    const int bh   = blockIdx.y, b = bh >> 4, h = bh & 15;
    const int qt   = gridDim.x - 1 - blockIdx.x;   // heavy tiles first
    const int q0   = qt * 64;

    const float* Qb = qkv + (size_t)b * SEQ * QKVCOLS + h * DK;
    const float* Kb = Qb + DMODEL;
    const float* Vb = Qb + 2 * DMODEL;

    for (int i = tid; i < 64 * 16; i += 128) {
        int row = i >> 4, c4 = (i & 15) * 4;
        float4 v = *(const float4*)(Qb + (size_t)(q0 + row) * QKVCOLS + c4);
        *(uint4*)(Ps + row * PST + c4) =
            make_uint4(f2tf(v.x * 0.125f), f2tf(v.y * 0.125f),
                       f2tf(v.z * 0.125f), f2tf(v.w * 0.125f));
    }
    __syncthreads();

    uint32_t aq[8][4];
    #pragma unroll
    for (int kc = 0; kc < 8; kc++) {
        const uint32_t* p = Ps + (warp * 16 + g) * PST + kc * 8 + tig;
        aq[kc][0] = p[0];
        aq[kc][1] = p[8 * PST];
        aq[kc][2] = p[4];
        aq[kc][3] = p[8 * PST + 4];
    }

    float m0 = -INFINITY, m1 = -INFINITY, l0 = 0.0f, l1 = 0.0f;
    float o[8][4];
    #pragma unroll
    for (int nt = 0; nt < 8; nt++)
        #pragma unroll
        for (int j = 0; j < 4; j++) o[nt][j] = 0.0f;

    for (int kt = 0; kt <= qt; kt++) {
        const int k0 = kt * 64;

        __syncthreads();
        for (int i = tid; i < 64 * 16; i += 128) {
            int row = i >> 4, c4 = (i & 15) * 4;
            float4 kv = *(const float4*)(Kb + (size_t)(k0 + row) * QKVCOLS + c4);
            *(uint4*)(Ks + row * KST + c4) =
                make_uint4(f2tf(kv.x), f2tf(kv.y), f2tf(kv.z), f2tf(kv.w));
            float4 vv = *(const float4*)(Vb + (size_t)(k0 + row) * QKVCOLS + c4);
            *(uint4*)(Vs + row * VST + c4) =
                make_uint4(f2tf(vv.x), f2tf(vv.y), f2tf(vv.z), f2tf(vv.w));
        }
        __syncthreads();

        float s[8][4];
        #pragma unroll
        for (int nt = 0; nt < 8; nt++) {
            s[nt][0] = s[nt][1] = s[nt][2] = s[nt][3] = 0.0f;
            #pragma unroll
            for (int kc = 0; kc < 8; kc++) {
                uint32_t bk[2];
                const uint32_t* p = Ks + (nt * 8 + g) * KST + kc * 8 + tig;
                bk[0] = p[0];
                bk[1] = p[4];
                mma8(s[nt], aq[kc], bk);
            }
        }

        if (kt == qt) {
            int r0 = warp * 16 + g;
            #pragma unroll
            for (int nt = 0; nt < 8; nt++) {
                int c = nt * 8 + 2 * tig;
                if (c     > r0)     s[nt][0] = -INFINITY;
                if (c + 1 > r0)     s[nt][1] = -INFINITY;
                if (c     > r0 + 8) s[nt][2] = -INFINITY;
                if (c + 1 > r0 + 8) s[nt][3] = -INFINITY;
            }
        }

        float mt0 = -INFINITY, mt1 = -INFINITY;
        #pragma unroll
        for (int nt = 0; nt < 8; nt++) {
            mt0 = fmaxf(mt0, fmaxf(s[nt][0], s[nt][1]));
            mt1 = fmaxf(mt1, fmaxf(s[nt][2], s[nt][3]));
        }
        mt0 = fmaxf(mt0, __shfl_xor_sync(0xffffffffu, mt0, 1));
        mt0 = fmaxf(mt0, __shfl_xor_sync(0xffffffffu, mt0, 2));
        mt1 = fmaxf(mt1, __shfl_xor_sync(0xffffffffu, mt1, 1));
        mt1 = fmaxf(mt1, __shfl_xor_sync(0xffffffffu, mt1, 2));

        float mn0 = fmaxf(m0, mt0), mn1 = fmaxf(m1, mt1);
        float al0 = __expf(m0 - mn0), al1 = __expf(m1 - mn1);

        float rs0 = 0.0f, rs1 = 0.0f;
        #pragma unroll
        for (int nt = 0; nt < 8; nt++) {
            s[nt][0] = __expf(s[nt][0] - mn0);
            s[nt][1] = __expf(s[nt][1] - mn0);
            s[nt][2] = __expf(s[nt][2] - mn1);
            s[nt][3] = __expf(s[nt][3] - mn1);
            rs0 += s[nt][0] + s[nt][1];
            rs1 += s[nt][2] + s[nt][3];
        }
        rs0 += __shfl_xor_sync(0xffffffffu, rs0, 1);
        rs0 += __shfl_xor_sync(0xffffffffu, rs0, 2);
        rs1 += __shfl_xor_sync(0xffffffffu, rs1, 1);
        rs1 += __shfl_xor_sync(0xffffffffu, rs1, 2);

        l0 = l0 * al0 + rs0;
        l1 = l1 * al1 + rs1;
        m0 = mn0;
        m1 = mn1;
        #pragma unroll
        for (int nt = 0; nt < 8; nt++) {
            o[nt][0] *= al0; o[nt][1] *= al0;
            o[nt][2] *= al1; o[nt][3] *= al1;
        }

        __syncwarp();
        {
            uint32_t* pr0 = Ps + (warp * 16 + g) * PST;
            uint32_t* pr1 = pr0 + 8 * PST;
            #pragma unroll
            for (int nt = 0; nt < 8; nt++) {
                int c = nt * 8 + 2 * tig;
                pr0[c]     = f2tf(s[nt][0]);
                pr0[c + 1] = f2tf(s[nt][1]);
                pr1[c]     = f2tf(s[nt][2]);
                pr1[c + 1] = f2tf(s[nt][3]);
            }
        }
        __syncwarp();

        #pragma unroll
        for (int kc = 0; kc < 8; kc++) {
            uint32_t ap[4];
            const uint32_t* pp = Ps + (warp * 16 + g) * PST + kc * 8 + tig;
            ap[0] = pp[0];
            ap[1] = pp[8 * PST];
            ap[2] = pp[4];
            ap[3] = pp[8 * PST + 4];
            #pragma unroll
            for (int nt = 0; nt < 8; nt++) {
                uint32_t bv[2];
                const uint32_t* pv = Vs + (kc * 8 + tig) * VST + nt * 8 + g;
                bv[0] = pv[0];
                bv[1] = pv[4 * VST];
                mma8(o[nt], ap, bv);
            }
        }
    }

    // normalize + tf32-round + write (GEMM2 streams these bits raw)
    float i0 = 1.0f / l0, i1 = 1.0f / l1;
    int r0 = q0 + warp * 16 + g;
    float* dst0 = outp + (size_t)(b * SEQ + r0) * DMODEL + h * DK;
    float* dst1 = dst0 + (size_t)8 * DMODEL;
    #pragma unroll
    for (int nt = 0; nt < 8; nt++) {
        int c = nt * 8 + 2 * tig;
        *(float2*)(dst0 + c) = make_float2(__uint_as_float(f2tf(o[nt][0] * i0)),
                                           __uint_as_float(f2tf(o[nt][1] * i0)));
        *(float2*)(dst1 + c) = make_float2(__uint_as_float(f2tf(o[nt][2] * i1)),
                                           __uint_as_float(f2tf(o[nt][3] * i1)));
    }
}

// =================================================================
// kernel_launch
// =================================================================
extern "C" void kernel_launch(void* const* d_in, const int* in_sizes, int n_in,
                              void* d_out, int out_size)
{
    const float* x     = (const float*)d_in[0];
    const float* w_qkv = (const float*)d_in[1];
    const float* w_out = (const float*)d_in[2];
    float*       out   = (float*)d_out;

    float *qkv_buf, *attn_buf, *xr, *wq, *wo;
    cudaGetSymbolAddress((void**)&qkv_buf,  g_qkv);
    cudaGetSymbolAddress((void**)&attn_buf, g_attn);
    cudaGetSymbolAddress((void**)&xr,       g_xr);
    cudaGetSymbolAddress((void**)&wq,       g_wq);
    cudaGetSymbolAddress((void**)&wo,       g_wo);

    cudaFuncSetAttribute(gemm_tf32_ca, cudaFuncAttributeMaxDynamicSharedMemorySize, GSMEM);
    const int flash_smem = (64 * PST + 64 * KST + 64 * VST) * 4;   // 53248 B
    cudaFuncSetAttribute(flash_tf32, cudaFuncAttributeMaxDynamicSharedMemorySize, flash_smem);

    // ---- prep: tf32 (RNA) rounding of all GEMM operands ----
    {
        int n4;
        n4 = MROWS * DMODEL / 4;
        round_tf32_kernel<<<(n4 + 255) / 256, 256>>>((const float4*)x, (float4*)xr, n4);
        n4 = DMODEL * QKVCOLS / 4;
        round_tf32_kernel<<<(n4 + 255) / 256, 256>>>((const float4*)w_qkv, (float4*)wq, n4);
        n4 = DMODEL * DMODEL / 4;
        round_tf32_kernel<<<(n4 + 255) / 256, 256>>>((const float4*)w_out, (float4*)wo, n4);
    }

    // 1) QKV projection: [8192,1024] @ [1024,3072]
    gemm_tf32_ca<<<dim3(QKVCOLS / 256, MROWS / 128), 256, GSMEM>>>(xr, wq, qkv_buf,
                                                                   QKVCOLS, DMODEL);
    // 2) causal flash attention
    flash_tf32<<<dim3(SEQ / 64, BATCH * NHEADS), 128, flash_smem>>>(qkv_buf, attn_buf);

    // 3) output projection: [8192,1024] @ [1024,1024]
    gemm_tf32_ca<<<dim3(DMODEL / 256, MROWS / 128), 256, GSMEM>>>(attn_buf, wo, out,
                                                                  DMODEL, DMODEL);
}